// round 10
// baseline (speedup 1.0000x reference)
#include <cuda_runtime.h>
#include <cuda_fp16.h>
#include <cstdint>
#include <float.h>

#define NG 5
#define NB 131072
#define NK 512
#define ND 64
#define CTA 512
#define RPC 1024                 // rows per CTA (2 per thread)
#define XBLK (NB / RPC)          // 128
#define NCTAS (NG * XBLK)        // 640
#define CAP 24
#define SC2 0.00390625f          // 2/512

__device__ double g_loss_sum[NG];
__device__ unsigned int g_done = 0;

__global__ __launch_bounds__(CTA, 1) void vq_h2_kernel(
    const float* __restrict__ feat,   // [G,B,D]
    const float* __restrict__ cb,     // [G,K,D]
    float* __restrict__ out_q,        // [G,B,D]
    float* __restrict__ out_loss,     // [G+1]
    float* __restrict__ out_idx,      // [G,B] as float
    int write_q, int write_loss, int write_idx)
{
    extern __shared__ char smem[];
    __half2* ch  = (__half2*)smem;                    // [64][512] bcast (512c,512c)
    float*   esq = (float*)(smem + (size_t)ND * NK * 4);   // [512]
    float*   red = esq + NK;                          // [16]

    const int tid = threadIdx.x;
    const int g = blockIdx.y;
    const int base_row = blockIdx.x * RPC;
    const float* cbg = cb + (size_t)g * NK * ND;
    const size_t gNB = (size_t)g * NB;

    // ---- Stage codebook: thread k -> row k; half2 bcast of 512*c; exact e_sq ----
    {
        const int k = tid;
        const float4* cp = (const float4*)(cbg + (size_t)k * ND);
        float acc = 0.f;
        #pragma unroll
        for (int i = 0; i < 16; i++) {
            float4 v = cp[i];
            acc = fmaf(v.x, v.x, acc);
            acc = fmaf(v.y, v.y, acc);
            acc = fmaf(v.z, v.z, acc);
            acc = fmaf(v.w, v.w, acc);
            const int d = 4 * i;
            ch[(size_t)(d + 0) * NK + k] = __float2half2_rn(v.x * 512.f);
            ch[(size_t)(d + 1) * NK + k] = __float2half2_rn(v.y * 512.f);
            ch[(size_t)(d + 2) * NK + k] = __float2half2_rn(v.z * 512.f);
            ch[(size_t)(d + 3) * NK + k] = __float2half2_rn(v.w * 512.f);
        }
        esq[k] = acc;
    }
    __syncthreads();

    // ---- Load 2 rows, pack xh2[d]=(x0_d,x1_d) fp16, exact x_sq, sum|x| ----
    const int row0 = base_row + tid;          // row1 = row0 + CTA
    __half2 xh2[ND];
    float xsq0 = 0.f, xsq1 = 0.f, sx0 = 0.f, sx1 = 0.f;
    {
        const float4* x0p = (const float4*)(feat + (gNB + row0) * ND);
        const float4* x1p = (const float4*)(feat + (gNB + row0 + CTA) * ND);
        #pragma unroll
        for (int i = 0; i < 16; i++) {
            float4 a = x0p[i];
            float4 b = x1p[i];
            xsq0 = fmaf(a.x, a.x, xsq0); xsq0 = fmaf(a.y, a.y, xsq0);
            xsq0 = fmaf(a.z, a.z, xsq0); xsq0 = fmaf(a.w, a.w, xsq0);
            xsq1 = fmaf(b.x, b.x, xsq1); xsq1 = fmaf(b.y, b.y, xsq1);
            xsq1 = fmaf(b.z, b.z, xsq1); xsq1 = fmaf(b.w, b.w, xsq1);
            sx0 += fabsf(a.x) + fabsf(a.y) + fabsf(a.z) + fabsf(a.w);
            sx1 += fabsf(b.x) + fabsf(b.y) + fabsf(b.z) + fabsf(b.w);
            xh2[4 * i + 0] = __floats2half2_rn(a.x, b.x);
            xh2[4 * i + 1] = __floats2half2_rn(a.y, b.y);
            xh2[4 * i + 2] = __floats2half2_rn(a.z, b.z);
            xh2[4 * i + 3] = __floats2half2_rn(a.w, b.w);
        }
    }
    // Provable fp16 filter error (scaled): 67*2^-11*sum|x|; eps = 2*bound*1.1
    const float eps0 = 2.85e-4f * sx0 + 1e-5f;
    const float eps1 = 2.85e-4f * sx1 + 1e-5f;

    // ---- HFMA2 filter: 8 codewords/block, scores s=esq-(2/512)*cross' ----
    float pmin0 = FLT_MAX, pmin1 = FLT_MAX;
    int cnt0 = 0, cnt1 = 0;
    int cnd0[CAP], cnd1[CAP];
    float cdv0[CAP], cdv1[CAP];
    #pragma unroll 1
    for (int kb = 0; kb < NK / 8; kb++) {
        __half2 a0 = __float2half2_rn(0.f), a1 = a0, a2 = a0, a3 = a0;
        __half2 a4 = a0, a5 = a0, a6 = a0, a7 = a0;
        const char* cbase = (const char*)(ch + kb * 8);
        #pragma unroll 8
        for (int d = 0; d < ND; d++) {
            uint4 t0 = *(const uint4*)(cbase + (size_t)d * (NK * 4));
            uint4 t1 = *(const uint4*)(cbase + (size_t)d * (NK * 4) + 16);
            __half2 xd = xh2[d];
            a0 = __hfma2(*(__half2*)&t0.x, xd, a0);
            a1 = __hfma2(*(__half2*)&t0.y, xd, a1);
            a2 = __hfma2(*(__half2*)&t0.z, xd, a2);
            a3 = __hfma2(*(__half2*)&t0.w, xd, a3);
            a4 = __hfma2(*(__half2*)&t1.x, xd, a4);
            a5 = __hfma2(*(__half2*)&t1.y, xd, a5);
            a6 = __hfma2(*(__half2*)&t1.z, xd, a6);
            a7 = __hfma2(*(__half2*)&t1.w, xd, a7);
        }
        const int k0 = kb * 8;
        #define COLLECT(J, ACC)                                                \
        {                                                                      \
            const float e = esq[k0 + J];                                       \
            float s0 = fmaf(-__low2float(ACC), SC2, e);                        \
            float s1 = fmaf(-__high2float(ACC), SC2, e);                       \
            pmin0 = fminf(pmin0, s0);                                          \
            pmin1 = fminf(pmin1, s1);                                          \
            if (s0 <= pmin0 + eps0) {                                          \
                if (cnt0 < CAP) { cnd0[cnt0] = k0 + J; cdv0[cnt0] = s0; }      \
                cnt0++;                                                        \
            }                                                                  \
            if (s1 <= pmin1 + eps1) {                                          \
                if (cnt1 < CAP) { cnd1[cnt1] = k0 + J; cdv1[cnt1] = s1; }      \
                cnt1++;                                                        \
            }                                                                  \
        }
        COLLECT(0, a0) COLLECT(1, a1) COLLECT(2, a2) COLLECT(3, a3)
        COLLECT(4, a4) COLLECT(5, a5) COLLECT(6, a6) COLLECT(7, a7)
        #undef COLLECT
    }

    // ---- Exact verify (validated fp32 sequential-d chain) + outputs per row ----
    float lsum = 0.f;
    #pragma unroll 1
    for (int r = 0; r < 2; r++) {
        const int row = row0 + r * CTA;
        const float4* xin = (const float4*)(feat + (gNB + row) * ND);
        float4 xv[16];
        #pragma unroll
        for (int i = 0; i < 16; i++) xv[i] = xin[i];
        const float xsq  = r ? xsq1 : xsq0;
        const float pmin = r ? pmin1 : pmin0;
        const float eps  = r ? eps1 : eps0;
        const int cnt    = r ? cnt1 : cnt0;
        const int* cnd   = r ? cnd1 : cnd0;
        const float* cdv = r ? cdv1 : cdv0;

        float best = FLT_MAX;
        int bk = 0;
        #define EXACT_K(kk)                                                    \
        {                                                                      \
            const float4* cp = (const float4*)(cbg + (size_t)(kk) * ND);       \
            float cr = 0.f;                                                    \
            _Pragma("unroll")                                                  \
            for (int i = 0; i < 16; i++) {                                     \
                float4 v = cp[i];                                              \
                cr = fmaf(xv[i].x, v.x, cr);                                   \
                cr = fmaf(xv[i].y, v.y, cr);                                   \
                cr = fmaf(xv[i].z, v.z, cr);                                   \
                cr = fmaf(xv[i].w, v.w, cr);                                   \
            }                                                                  \
            float dk = (xsq + esq[kk]) - 2.0f * cr;                            \
            if (dk < best || (dk == best && (kk) < bk)) { best = dk; bk = (kk); } \
        }
        if (cnt > CAP) {
            for (int k = 0; k < NK; k++) EXACT_K(k);
        } else {
            const float th = pmin + eps;
            for (int i = 0; i < cnt; i++) {
                if (cdv[i] <= th) { int k = cnd[i]; EXACT_K(k); }
            }
        }
        #undef EXACT_K

        const float4* qp = (const float4*)(cbg + (size_t)bk * ND);
        float4* oq = (float4*)(out_q + (gNB + row) * ND);
        #pragma unroll
        for (int i = 0; i < 16; i++) {
            float4 qv = qp[i], fv = xv[i];
            float dx0 = qv.x - fv.x, dx1 = qv.y - fv.y;
            float dx2 = qv.z - fv.z, dx3 = qv.w - fv.w;
            lsum = fmaf(dx0, dx0, lsum);
            lsum = fmaf(dx1, dx1, lsum);
            lsum = fmaf(dx2, dx2, lsum);
            lsum = fmaf(dx3, dx3, lsum);
            if (write_q)
                oq[i] = make_float4(fv.x + dx0, fv.y + dx1, fv.z + dx2, fv.w + dx3);
        }
        if (write_idx) out_idx[gNB + row] = (float)bk;
    }

    // ---- Loss: warp shuffle -> shared -> double atomic; last CTA finalizes ----
    #pragma unroll
    for (int off = 16; off > 0; off >>= 1)
        lsum += __shfl_xor_sync(0xFFFFFFFFu, lsum, off);
    if ((tid & 31) == 0) red[tid >> 5] = lsum;
    __syncthreads();
    if (tid == 0) {
        double s = 0.0;
        #pragma unroll
        for (int w = 0; w < CTA / 32; w++) s += (double)red[w];
        atomicAdd(&g_loss_sum[g], s);
        __threadfence();
        unsigned int t = atomicAdd(&g_done, 1u);
        if (t == NCTAS - 1) {
            __threadfence();
            if (write_loss) {
                const double inv = 1.25 / ((double)NB * (double)ND);
                float tot = 0.f;
                for (int g2 = 0; g2 < NG; g2++) {
                    float pl = (float)(g_loss_sum[g2] * inv);
                    out_loss[g2] = pl;
                    tot += pl;
                }
                out_loss[NG] = tot;
            }
            for (int g2 = 0; g2 < NG; g2++) g_loss_sum[g2] = 0.0;
            g_done = 0;
        }
    }
}

extern "C" void kernel_launch(void* const* d_in, const int* in_sizes, int n_in,
                              void* d_out, int out_size) {
    const float* feat = (const float*)d_in[0];
    const float* cb   = (const float*)d_in[1];
    if (n_in >= 2 && in_sizes[0] == NG * NK * ND) {
        const float* t = feat; feat = cb; cb = t;
    }
    float* out = (float*)d_out;

    const long long q_elems   = (long long)NG * NB * ND;
    const long long idx_elems = (long long)NG * NB;
    const long long full_sz   = q_elems + NG + 1 + idx_elems;
    const int write_q    = ((long long)out_size >= q_elems);
    const int write_loss = ((long long)out_size >= q_elems + NG + 1);
    const int write_idx  = ((long long)out_size >= full_sz);

    const int smem_bytes = ND * NK * 4 + NK * 4 + 16 * 4;   // 133,184 B
    cudaFuncSetAttribute(vq_h2_kernel,
                         cudaFuncAttributeMaxDynamicSharedMemorySize, smem_bytes);

    dim3 grid(XBLK, NG);
    float* out_loss = out + q_elems;
    float* out_idx  = out + q_elems + NG + 1;
    vq_h2_kernel<<<grid, CTA, smem_bytes>>>(feat, cb, out, out_loss, out_idx,
                                            write_q, write_loss, write_idx);
}

// round 11
// speedup vs baseline: 1.0769x; 1.0769x over previous
#include <cuda_runtime.h>
#include <cuda_fp16.h>
#include <cstdint>
#include <float.h>

#define NG 5
#define NB 131072
#define NK 512
#define ND 64
#define CTA 256
#define RPC 512                  // rows per CTA (2 per thread)
#define XBLK (NB / RPC)          // 256
#define NCTAS (NG * XBLK)        // 1280
#define SC2 0.00390625f          // 2/512
#define EPSC 1.6e-4f             // per-row eps = EPSC * sum|x| + 1e-5

__device__ double g_loss_sum[NG];
__device__ unsigned int g_done = 0;

__device__ __forceinline__ __half2 H2(uint32_t u) { return *(__half2*)&u; }

__global__ __launch_bounds__(CTA, 2) void vq_h2_kernel(
    const float* __restrict__ feat,   // [G,B,D]
    const float* __restrict__ cb,     // [G,K,D]
    float* __restrict__ out_q,        // [G,B,D]
    float* __restrict__ out_loss,     // [G+1]
    float* __restrict__ out_idx,      // [G,B] as float
    int write_q, int write_loss, int write_idx)
{
    extern __shared__ char smem[];
    uint32_t* cp  = (uint32_t*)smem;                 // [512][32] half2 (512c_d,512c_{d+1})
    float*    esq = (float*)(smem + NK * 32 * 4);    // [512]
    float*    red = esq + NK;                        // [8]

    const int tid = threadIdx.x;
    const int g = blockIdx.y;
    const int base_row = blockIdx.x * RPC;
    const float* cbg = cb + (size_t)g * NK * ND;
    const size_t gNB = (size_t)g * NB;

    // ---- Stage codebook: 2 codewords/thread; exact e_sq (validated chain) ----
    #pragma unroll
    for (int s2 = 0; s2 < 2; s2++) {
        const int k = tid + s2 * CTA;
        const float4* cpg = (const float4*)(cbg + (size_t)k * ND);
        uint32_t* dst = cp + k * 32;
        float acc = 0.f;
        #pragma unroll
        for (int i = 0; i < 16; i++) {
            float4 v = cpg[i];
            acc = fmaf(v.x, v.x, acc);
            acc = fmaf(v.y, v.y, acc);
            acc = fmaf(v.z, v.z, acc);
            acc = fmaf(v.w, v.w, acc);
            __half2 h0 = __floats2half2_rn(v.x * 512.f, v.y * 512.f);
            __half2 h1 = __floats2half2_rn(v.z * 512.f, v.w * 512.f);
            dst[2 * i]     = *(uint32_t*)&h0;
            dst[2 * i + 1] = *(uint32_t*)&h1;
        }
        esq[k] = acc;
    }
    __syncthreads();

    // ---- Load 2 rows, pack (d,d+1) half2 pairs, sum|x| for eps ----
    const int row0 = base_row + tid;          // row1 = row0 + CTA
    __half2 xa[32], xb[32];
    float sx0 = 0.f, sx1 = 0.f;
    {
        const float4* x0p = (const float4*)(feat + (gNB + row0) * ND);
        const float4* x1p = (const float4*)(feat + (gNB + row0 + CTA) * ND);
        #pragma unroll
        for (int i = 0; i < 16; i++) {
            float4 a = x0p[i];
            float4 b = x1p[i];
            sx0 += fabsf(a.x) + fabsf(a.y) + fabsf(a.z) + fabsf(a.w);
            sx1 += fabsf(b.x) + fabsf(b.y) + fabsf(b.z) + fabsf(b.w);
            xa[2 * i]     = __floats2half2_rn(a.x, a.y);
            xa[2 * i + 1] = __floats2half2_rn(a.z, a.w);
            xb[2 * i]     = __floats2half2_rn(b.x, b.y);
            xb[2 * i + 1] = __floats2half2_rn(b.z, b.w);
        }
    }
    const float eps0 = EPSC * sx0 + 1e-5f;
    const float eps1 = EPSC * sx1 + 1e-5f;

    // ---- HFMA2 filter: 4 codewords x 2 rows per block; top-4 per row ----
    float t00 = FLT_MAX, t01 = FLT_MAX, t02 = FLT_MAX, t03 = FLT_MAX;
    float t10 = FLT_MAX, t11 = FLT_MAX, t12 = FLT_MAX, t13 = FLT_MAX;
    int i00 = 0, i01 = 0, i02 = 0, i03 = 0;
    int i10 = 0, i11 = 0, i12 = 0, i13 = 0;

    #define INS(s, k, T0, T1, T2, T3, I0, I1, I2, I3)                          \
    if ((s) < T3) {                                                            \
        if ((s) < T1) {                                                        \
            T3 = T2; I3 = I2; T2 = T1; I2 = I1;                                \
            if ((s) < T0) { T1 = T0; I1 = I0; T0 = (s); I0 = (k); }            \
            else          { T1 = (s); I1 = (k); }                              \
        } else {                                                               \
            if ((s) < T2) { T3 = T2; I3 = I2; T2 = (s); I2 = (k); }            \
            else          { T3 = (s); I3 = (k); }                              \
        }                                                                      \
    }

    #pragma unroll 1
    for (int kb = 0; kb < NK / 4; kb++) {
        const int k0 = kb * 4;
        const uint4* p0 = (const uint4*)(cp + (k0 + 0) * 32);
        const uint4* p1 = (const uint4*)(cp + (k0 + 1) * 32);
        const uint4* p2 = (const uint4*)(cp + (k0 + 2) * 32);
        const uint4* p3 = (const uint4*)(cp + (k0 + 3) * 32);
        __half2 z = __float2half2_rn(0.f);
        __half2 a0 = z, a1 = z, a2 = z, a3 = z, a4 = z, a5 = z, a6 = z, a7 = z;
        #pragma unroll
        for (int c = 0; c < 8; c++) {
            uint4 u0 = p0[c], u1 = p1[c], u2 = p2[c], u3 = p3[c];
            __half2 xA, xB;
            #define STEP(W)                                                    \
                a0 = __hfma2(H2(u0.W), xA, a0);                                \
                a1 = __hfma2(H2(u0.W), xB, a1);                                \
                a2 = __hfma2(H2(u1.W), xA, a2);                                \
                a3 = __hfma2(H2(u1.W), xB, a3);                                \
                a4 = __hfma2(H2(u2.W), xA, a4);                                \
                a5 = __hfma2(H2(u2.W), xB, a5);                                \
                a6 = __hfma2(H2(u3.W), xA, a6);                                \
                a7 = __hfma2(H2(u3.W), xB, a7);
            xA = xa[4 * c + 0]; xB = xb[4 * c + 0]; STEP(x)
            xA = xa[4 * c + 1]; xB = xb[4 * c + 1]; STEP(y)
            xA = xa[4 * c + 2]; xB = xb[4 * c + 2]; STEP(z)
            xA = xa[4 * c + 3]; xB = xb[4 * c + 3]; STEP(w)
            #undef STEP
        }
        const float e0 = esq[k0], e1 = esq[k0 + 1], e2 = esq[k0 + 2], e3 = esq[k0 + 3];
        #define SCORE(ACC, E) fmaf(-(__low2float(ACC) + __high2float(ACC)), SC2, (E))
        float s;
        s = SCORE(a0, e0); INS(s, k0 + 0, t00, t01, t02, t03, i00, i01, i02, i03)
        s = SCORE(a2, e1); INS(s, k0 + 1, t00, t01, t02, t03, i00, i01, i02, i03)
        s = SCORE(a4, e2); INS(s, k0 + 2, t00, t01, t02, t03, i00, i01, i02, i03)
        s = SCORE(a6, e3); INS(s, k0 + 3, t00, t01, t02, t03, i00, i01, i02, i03)
        s = SCORE(a1, e0); INS(s, k0 + 0, t10, t11, t12, t13, i10, i11, i12, i13)
        s = SCORE(a3, e1); INS(s, k0 + 1, t10, t11, t12, t13, i10, i11, i12, i13)
        s = SCORE(a5, e2); INS(s, k0 + 2, t10, t11, t12, t13, i10, i11, i12, i13)
        s = SCORE(a7, e3); INS(s, k0 + 3, t10, t11, t12, t13, i10, i11, i12, i13)
        #undef SCORE
    }
    #undef INS

    // ---- Exact verify (validated fp32 sequential-d chain) + outputs per row ----
    float lsum = 0.f;
    #pragma unroll 1
    for (int r = 0; r < 2; r++) {
        const int row = row0 + r * CTA;
        const float4* xin = (const float4*)(feat + (gNB + row) * ND);
        float4 xv[16];
        float xsq = 0.f;
        #pragma unroll
        for (int i = 0; i < 16; i++) {
            float4 v = xin[i];
            xv[i] = v;
            xsq = fmaf(v.x, v.x, xsq);
            xsq = fmaf(v.y, v.y, xsq);
            xsq = fmaf(v.z, v.z, xsq);
            xsq = fmaf(v.w, v.w, xsq);
        }
        const float v0 = r ? t10 : t00, v1 = r ? t11 : t01;
        const float v2 = r ? t12 : t02, v3 = r ? t13 : t03;
        const int   c0 = r ? i10 : i00, c1 = r ? i11 : i01;
        const int   c2 = r ? i12 : i02, c3 = r ? i13 : i03;
        const float th = v0 + (r ? eps1 : eps0);

        float best = FLT_MAX;
        int bk = 0;
        #define EXACT_K(kk)                                                    \
        {                                                                      \
            const float4* cpk = (const float4*)(cbg + (size_t)(kk) * ND);      \
            float cr = 0.f;                                                    \
            _Pragma("unroll")                                                  \
            for (int i = 0; i < 16; i++) {                                     \
                float4 v = cpk[i];                                             \
                cr = fmaf(xv[i].x, v.x, cr);                                   \
                cr = fmaf(xv[i].y, v.y, cr);                                   \
                cr = fmaf(xv[i].z, v.z, cr);                                   \
                cr = fmaf(xv[i].w, v.w, cr);                                   \
            }                                                                  \
            float dk = (xsq + esq[kk]) - 2.0f * cr;                            \
            if (dk < best || (dk == best && (kk) < bk)) { best = dk; bk = (kk); } \
        }
        if (v3 <= th) {
            for (int k = 0; k < NK; k++) EXACT_K(k);       // provable overflow
        } else {
            EXACT_K(c0);
            if (v1 <= th) EXACT_K(c1);
            if (v2 <= th) EXACT_K(c2);
            if (v3 <= th) EXACT_K(c3);
        }
        #undef EXACT_K

        const float4* qp = (const float4*)(cbg + (size_t)bk * ND);
        float4* oq = (float4*)(out_q + (gNB + row) * ND);
        #pragma unroll
        for (int i = 0; i < 16; i++) {
            float4 qv = qp[i], fv = xv[i];
            float dx0 = qv.x - fv.x, dx1 = qv.y - fv.y;
            float dx2 = qv.z - fv.z, dx3 = qv.w - fv.w;
            lsum = fmaf(dx0, dx0, lsum);
            lsum = fmaf(dx1, dx1, lsum);
            lsum = fmaf(dx2, dx2, lsum);
            lsum = fmaf(dx3, dx3, lsum);
            if (write_q)
                oq[i] = make_float4(fv.x + dx0, fv.y + dx1, fv.z + dx2, fv.w + dx3);
        }
        if (write_idx) out_idx[gNB + row] = (float)bk;
    }

    // ---- Loss: warp shuffle -> shared -> double atomic; last CTA finalizes ----
    #pragma unroll
    for (int off = 16; off > 0; off >>= 1)
        lsum += __shfl_xor_sync(0xFFFFFFFFu, lsum, off);
    if ((tid & 31) == 0) red[tid >> 5] = lsum;
    __syncthreads();
    if (tid == 0) {
        double s = 0.0;
        #pragma unroll
        for (int w = 0; w < CTA / 32; w++) s += (double)red[w];
        atomicAdd(&g_loss_sum[g], s);
        __threadfence();
        unsigned int t = atomicAdd(&g_done, 1u);
        if (t == NCTAS - 1) {
            __threadfence();
            if (write_loss) {
                const double inv = 1.25 / ((double)NB * (double)ND);
                float tot = 0.f;
                for (int g2 = 0; g2 < NG; g2++) {
                    float pl = (float)(g_loss_sum[g2] * inv);
                    out_loss[g2] = pl;
                    tot += pl;
                }
                out_loss[NG] = tot;
            }
            for (int g2 = 0; g2 < NG; g2++) g_loss_sum[g2] = 0.0;
            g_done = 0;
        }
    }
}

extern "C" void kernel_launch(void* const* d_in, const int* in_sizes, int n_in,
                              void* d_out, int out_size) {
    const float* feat = (const float*)d_in[0];
    const float* cb   = (const float*)d_in[1];
    if (n_in >= 2 && in_sizes[0] == NG * NK * ND) {
        const float* t = feat; feat = cb; cb = t;
    }
    float* out = (float*)d_out;

    const long long q_elems   = (long long)NG * NB * ND;
    const long long idx_elems = (long long)NG * NB;
    const long long full_sz   = q_elems + NG + 1 + idx_elems;
    const int write_q    = ((long long)out_size >= q_elems);
    const int write_loss = ((long long)out_size >= q_elems + NG + 1);
    const int write_idx  = ((long long)out_size >= full_sz);

    const int smem_bytes = NK * 32 * 4 + NK * 4 + 32;   // 67,616 B
    cudaFuncSetAttribute(vq_h2_kernel,
                         cudaFuncAttributeMaxDynamicSharedMemorySize, smem_bytes);

    dim3 grid(XBLK, NG);
    float* out_loss = out + q_elems;
    float* out_idx  = out + q_elems + NG + 1;
    vq_h2_kernel<<<grid, CTA, smem_bytes>>>(feat, cb, out, out_loss, out_idx,
                                            write_q, write_loss, write_idx);
}

// round 12
// speedup vs baseline: 3.5659x; 3.3114x over previous
#include <cuda_runtime.h>
#include <cuda_fp16.h>
#include <cstdint>
#include <float.h>

#define NG 5
#define NB 131072
#define NK 512
#define ND 64
#define CTA 256
#define XBLK (NB / CTA)          // 512 (1 row per thread)
#define NCTAS (NG * XBLK)        // 2560
#define SC2 0.00390625f          // 2/512

__device__ double g_loss_sum[NG];
__device__ unsigned int g_done = 0;

__device__ __forceinline__ __half2 H2(uint32_t u) { return *(__half2*)&u; }

__global__ __launch_bounds__(CTA, 2) void vq_h2f_kernel(
    const float* __restrict__ feat,   // [G,B,D]
    const float* __restrict__ cb,     // [G,K,D]
    float* __restrict__ out_q,        // [G,B,D]
    float* __restrict__ out_loss,     // [G+1]
    float* __restrict__ out_idx,      // [G,B] as float
    int write_q, int write_loss, int write_idx)
{
    extern __shared__ char smem[];
    uint32_t* cp  = (uint32_t*)smem;               // [512][32] half2 (512c_d,512c_{d+1})
    float*    esq = (float*)(smem + NK * 32 * 4);  // [512]
    float*    red = esq + NK;                      // [8]

    const int tid = threadIdx.x;
    const int g = blockIdx.y;
    const float* cbg = cb + (size_t)g * NK * ND;
    const size_t gNB = (size_t)g * NB;

    // ---- Stage codebook (2 cw/thread): half2 pairs of 512*c; exact e_sq ----
    #pragma unroll
    for (int s2 = 0; s2 < 2; s2++) {
        const int k = tid + s2 * CTA;
        const float4* cpg = (const float4*)(cbg + (size_t)k * ND);
        uint32_t* dst = cp + k * 32;
        float acc = 0.f;
        #pragma unroll
        for (int i = 0; i < 16; i++) {
            float4 v = cpg[i];
            acc = fmaf(v.x, v.x, acc);
            acc = fmaf(v.y, v.y, acc);
            acc = fmaf(v.z, v.z, acc);
            acc = fmaf(v.w, v.w, acc);
            __half2 h0 = __floats2half2_rn(v.x * 512.f, v.y * 512.f);
            __half2 h1 = __floats2half2_rn(v.z * 512.f, v.w * 512.f);
            dst[2 * i]     = *(uint32_t*)&h0;
            dst[2 * i + 1] = *(uint32_t*)&h1;
        }
        esq[k] = acc;
    }
    __syncthreads();

    // ---- Load row, pack (d,d+1) half2, exact x_sq (validated chain) ----
    const int row = blockIdx.x * CTA + tid;
    __half2 xh[32];
    float xsq = 0.f;
    {
        const float4* xp = (const float4*)(feat + (gNB + row) * ND);
        #pragma unroll
        for (int i = 0; i < 16; i++) {
            float4 a = xp[i];
            xsq = fmaf(a.x, a.x, xsq);
            xsq = fmaf(a.y, a.y, xsq);
            xsq = fmaf(a.z, a.z, xsq);
            xsq = fmaf(a.w, a.w, xsq);
            xh[2 * i]     = __floats2half2_rn(a.x, a.y);
            xh[2 * i + 1] = __floats2half2_rn(a.z, a.w);
        }
    }
    // statistical eps: 8 * 2^-11 * sqrt(11.5*xsq) scaled by SC2
    const float eps = 1.526e-5f * __fsqrt_rn(11.5f * xsq) + 2e-6f;

    // ---- HFMA2 filter, top-4 tracking ----
    float t0 = FLT_MAX, t1 = FLT_MAX, t2 = FLT_MAX, t3 = FLT_MAX;
    int c0 = 0, c1 = 0, c2 = 0, c3 = 0;
    #define INS(s, k)                                                          \
    if ((s) < t3) {                                                            \
        if ((s) < t1) {                                                        \
            t3 = t2; c3 = c2; t2 = t1; c2 = c1;                                \
            if ((s) < t0) { t1 = t0; c1 = c0; t0 = (s); c0 = (k); }            \
            else          { t1 = (s); c1 = (k); }                              \
        } else {                                                               \
            if ((s) < t2) { t3 = t2; c3 = c2; t2 = (s); c2 = (k); }            \
            else          { t3 = (s); c3 = (k); }                              \
        }                                                                      \
    }

    #pragma unroll 1
    for (int kb = 0; kb < NK / 4; kb++) {
        const int k0 = kb * 4;
        const uint4* p0 = (const uint4*)(cp + (k0 + 0) * 32);
        const uint4* p1 = (const uint4*)(cp + (k0 + 1) * 32);
        const uint4* p2 = (const uint4*)(cp + (k0 + 2) * 32);
        const uint4* p3 = (const uint4*)(cp + (k0 + 3) * 32);
        __half2 z = __float2half2_rn(0.f);
        __half2 a0 = z, a1 = z, a2 = z, a3 = z;
        #pragma unroll
        for (int c = 0; c < 8; c++) {
            uint4 u0 = p0[c], u1 = p1[c], u2 = p2[c], u3 = p3[c];
            __half2 x0 = xh[4 * c + 0], x1 = xh[4 * c + 1];
            __half2 x2 = xh[4 * c + 2], x3 = xh[4 * c + 3];
            a0 = __hfma2(H2(u0.x), x0, a0);
            a1 = __hfma2(H2(u1.x), x0, a1);
            a2 = __hfma2(H2(u2.x), x0, a2);
            a3 = __hfma2(H2(u3.x), x0, a3);
            a0 = __hfma2(H2(u0.y), x1, a0);
            a1 = __hfma2(H2(u1.y), x1, a1);
            a2 = __hfma2(H2(u2.y), x1, a2);
            a3 = __hfma2(H2(u3.y), x1, a3);
            a0 = __hfma2(H2(u0.z), x2, a0);
            a1 = __hfma2(H2(u1.z), x2, a1);
            a2 = __hfma2(H2(u2.z), x2, a2);
            a3 = __hfma2(H2(u3.z), x2, a3);
            a0 = __hfma2(H2(u0.w), x3, a0);
            a1 = __hfma2(H2(u1.w), x3, a1);
            a2 = __hfma2(H2(u2.w), x3, a2);
            a3 = __hfma2(H2(u3.w), x3, a3);
        }
        float s;
        s = fmaf(-(__low2float(a0) + __high2float(a0)), SC2, esq[k0 + 0]); INS(s, k0 + 0)
        s = fmaf(-(__low2float(a1) + __high2float(a1)), SC2, esq[k0 + 1]); INS(s, k0 + 1)
        s = fmaf(-(__low2float(a2) + __high2float(a2)), SC2, esq[k0 + 2]); INS(s, k0 + 2)
        s = fmaf(-(__low2float(a3) + __high2float(a3)), SC2, esq[k0 + 3]); INS(s, k0 + 3)
    }
    #undef INS

    // ---- Selection: single candidate -> done; else exact fp32 ordering ----
    const float4* xin = (const float4*)(feat + (gNB + row) * ND);
    float4 xv[16];
    #pragma unroll
    for (int i = 0; i < 16; i++) xv[i] = xin[i];

    int bk = c0;
    const float th = t0 + eps;
    if (t1 <= th) {
        float best = FLT_MAX;
        bk = 0;
        #define EXACT_K(kk)                                                    \
        {                                                                      \
            const float4* cpk = (const float4*)(cbg + (size_t)(kk) * ND);      \
            float cr = 0.f;                                                    \
            _Pragma("unroll")                                                  \
            for (int i = 0; i < 16; i++) {                                     \
                float4 v = cpk[i];                                             \
                cr = fmaf(xv[i].x, v.x, cr);                                   \
                cr = fmaf(xv[i].y, v.y, cr);                                   \
                cr = fmaf(xv[i].z, v.z, cr);                                   \
                cr = fmaf(xv[i].w, v.w, cr);                                   \
            }                                                                  \
            float dk = (xsq + esq[kk]) - 2.0f * cr;                            \
            if (dk < best || (dk == best && (kk) < bk)) { best = dk; bk = (kk); } \
        }
        if (t3 <= th) {
            bk = 0; best = FLT_MAX;
            for (int k = 0; k < NK; k++) EXACT_K(k);   // provable overflow
        } else {
            best = FLT_MAX; bk = 0;
            EXACT_K(c0);
            EXACT_K(c1);
            if (t2 <= th) EXACT_K(c2);
            if (t3 <= th) EXACT_K(c3);
        }
        #undef EXACT_K
    }

    // ---- Outputs: quantized_st = x + (q - x), index, loss partial ----
    float lsum = 0.f;
    {
        const float4* qp = (const float4*)(cbg + (size_t)bk * ND);
        float4* oq = (float4*)(out_q + (gNB + row) * ND);
        #pragma unroll
        for (int i = 0; i < 16; i++) {
            float4 qv = qp[i], fv = xv[i];
            float dx0 = qv.x - fv.x, dx1 = qv.y - fv.y;
            float dx2 = qv.z - fv.z, dx3 = qv.w - fv.w;
            lsum = fmaf(dx0, dx0, lsum);
            lsum = fmaf(dx1, dx1, lsum);
            lsum = fmaf(dx2, dx2, lsum);
            lsum = fmaf(dx3, dx3, lsum);
            if (write_q)
                oq[i] = make_float4(fv.x + dx0, fv.y + dx1, fv.z + dx2, fv.w + dx3);
        }
    }
    if (write_idx) out_idx[gNB + row] = (float)bk;

    // ---- Loss: warp shuffle -> shared -> double atomic; last CTA finalizes ----
    #pragma unroll
    for (int off = 16; off > 0; off >>= 1)
        lsum += __shfl_xor_sync(0xFFFFFFFFu, lsum, off);
    if ((tid & 31) == 0) red[tid >> 5] = lsum;
    __syncthreads();
    if (tid == 0) {
        double s = 0.0;
        #pragma unroll
        for (int w = 0; w < CTA / 32; w++) s += (double)red[w];
        atomicAdd(&g_loss_sum[g], s);
        __threadfence();
        unsigned int t = atomicAdd(&g_done, 1u);
        if (t == NCTAS - 1) {
            __threadfence();
            if (write_loss) {
                const double inv = 1.25 / ((double)NB * (double)ND);
                float tot = 0.f;
                for (int g2 = 0; g2 < NG; g2++) {
                    float pl = (float)(g_loss_sum[g2] * inv);
                    out_loss[g2] = pl;
                    tot += pl;
                }
                out_loss[NG] = tot;
            }
            for (int g2 = 0; g2 < NG; g2++) g_loss_sum[g2] = 0.0;
            g_done = 0;
        }
    }
}

extern "C" void kernel_launch(void* const* d_in, const int* in_sizes, int n_in,
                              void* d_out, int out_size) {
    const float* feat = (const float*)d_in[0];
    const float* cb   = (const float*)d_in[1];
    if (n_in >= 2 && in_sizes[0] == NG * NK * ND) {
        const float* t = feat; feat = cb; cb = t;
    }
    float* out = (float*)d_out;

    const long long q_elems   = (long long)NG * NB * ND;
    const long long idx_elems = (long long)NG * NB;
    const long long full_sz   = q_elems + NG + 1 + idx_elems;
    const int write_q    = ((long long)out_size >= q_elems);
    const int write_loss = ((long long)out_size >= q_elems + NG + 1);
    const int write_idx  = ((long long)out_size >= full_sz);

    const int smem_bytes = NK * 32 * 4 + NK * 4 + 32;   // 67,616 B
    cudaFuncSetAttribute(vq_h2f_kernel,
                         cudaFuncAttributeMaxDynamicSharedMemorySize, smem_bytes);

    dim3 grid(XBLK, NG);
    float* out_loss = out + q_elems;
    float* out_idx  = out + q_elems + NG + 1;
    vq_h2f_kernel<<<grid, CTA, smem_bytes>>>(feat, cb, out, out_loss, out_idx,
                                             write_q, write_loss, write_idx);
}